// round 8
// baseline (speedup 1.0000x reference)
#include <cuda_runtime.h>
#include <cuda_bf16.h>
#include <cstdint>

// TinyRNN (GRU): B=4096, T=2048, I=3, H=4, O=2
// 4 lanes per element (one per hidden unit) AND 4 elements per thread (k=4 ILP
// interleave): the 4 independent recurrences in one instruction stream hide the
// serial chain latency (tanh->fma->tanh->update->shfl) that bound Round 5.
// 32 blocks x 128 threads; block covers 128 elements; lane-group g of warp w
// handles elements {w*8+g + 32j}.

#define BB 4096
#define TT 2048
#define CHUNK 16
#define EPB 128              // elements per block
#define KK 4                 // elements per thread
#define THREADS 128
#define SXS 52               // sx row stride in floats (CHUNK*3 + 4)
#define SOS 36               // so row stride in floats (CHUNK*2 + 4)

__device__ __forceinline__ float tanh_ap(float x) {
    float r;
    asm("tanh.approx.f32 %0, %1;" : "=f"(r) : "f"(x));
    return r;
}

__global__ __launch_bounds__(THREADS, 1)
void tiny_gru6_kernel(const float* __restrict__ in,     // (B,T,I)
                      const float* __restrict__ W_in,   // (I,3H)
                      const float* __restrict__ W_h,    // (H,3H)
                      const float* __restrict__ bias,   // (6H,)
                      const float* __restrict__ dec_W,  // (H,O)
                      const float* __restrict__ dec_b,  // (O,)
                      float* __restrict__ out)          // (B,T,O)
{
    __shared__ float sx[EPB * SXS];   // staged inputs  [elem][CHUNK*3]
    __shared__ float so[EPB * SOS];   // staged outputs [elem][CHUNK*2]

    const int tid   = threadIdx.x;
    const int u     = tid & 3;        // hidden unit
    const int gbase = tid >> 2;       // lane-group id within block (0..31)
    const int b0    = blockIdx.x * EPB;

    // ---- weight folding ----
    // r,z: sigmoid(x)=0.5+0.5*tanh(x/2) -> weights*0.5, biases(in+h)*0.5 in f
    // n:   tanh direct; recurrent part *0.5 so r*g_n = G2 + tanh(s_r)*G2
    float wiu[3][3];
#pragma unroll
    for (int g = 0; g < 3; g++) {
        float s = (g == 2) ? 1.0f : 0.5f;
#pragma unroll
        for (int i = 0; i < 3; i++) wiu[g][i] = W_in[i * 12 + g * 4 + u] * s;
    }
    float whu[3][4];
#pragma unroll
    for (int g = 0; g < 3; g++)
#pragma unroll
        for (int j = 0; j < 4; j++) whu[g][j] = W_h[j * 12 + g * 4 + u] * 0.5f;

    float bfu0 = 0.5f * (bias[0 + u] + bias[12 + u]);
    float bfu1 = 0.5f * (bias[4 + u] + bias[16 + u]);
    float bfu2 = bias[8 + u];
    float bh2u = 0.5f * bias[20 + u];

    const int o = u & 1;              // decoder slot; only u<2 lanes store
    float dwv0 = dec_W[0 * 2 + o], dwv1 = dec_W[1 * 2 + o];
    float dwv2 = dec_W[2 * 2 + o], dwv3 = dec_W[3 * 2 + o];
    float dbv  = dec_b[o];

    // per-element recurrent state
    float hp[KK], h0[KK], h1[KK], h2[KK], h3[KK];
#pragma unroll
    for (int j = 0; j < KK; j++) { hp[j] = h0[j] = h1[j] = h2[j] = h3[j] = 0.0f; }

    const float* inb  = in  + (size_t)b0 * TT * 3;
    float*       outb = out + (size_t)b0 * TT * 2;

    // per-thread smem bases for its 4 elements
    const float* xb[KK];
    float*       ob[KK];
#pragma unroll
    for (int j = 0; j < KK; j++) {
        xb[j] = &sx[(gbase + 32 * j) * SXS];
        ob[j] = &so[(gbase + 32 * j) * SOS];
    }

    for (int tc = 0; tc < TT; tc += CHUNK) {
        // ---- stage input tile: coalesced float4 LDG -> smem ----
#pragma unroll
        for (int m = 0; m < 12; m++) {
            int idx = tid + m * THREADS;          // 0..1535
            int r   = idx / 12;                   // element 0..127
            int s4  = idx - r * 12;               // float4 index 0..11
            float4 v = *(const float4*)(inb + (size_t)r * TT * 3 + tc * 3 + s4 * 4);
            *(float4*)&sx[r * SXS + s4 * 4] = v;
        }
        __syncthreads();

        // ---- recurrence: 4 interleaved elements per thread ----
#pragma unroll 4
        for (int tt = 0; tt < CHUNK; tt++) {
#pragma unroll
            for (int j = 0; j < KK; j++) {
                float x0 = xb[j][tt * 3 + 0];
                float x1 = xb[j][tt * 3 + 1];
                float x2 = xb[j][tt * 3 + 2];

                float f0 = fmaf(x2, wiu[0][2], fmaf(x1, wiu[0][1], fmaf(x0, wiu[0][0], bfu0)));
                float f1 = fmaf(x2, wiu[1][2], fmaf(x1, wiu[1][1], fmaf(x0, wiu[1][0], bfu1)));
                float f2 = fmaf(x2, wiu[2][2], fmaf(x1, wiu[2][1], fmaf(x0, wiu[2][0], bfu2)));

                float ga0 = fmaf(h1[j], whu[0][1], fmaf(h0[j], whu[0][0], f0));
                float gb0 = fmaf(h3[j], whu[0][3], h2[j] * whu[0][2]);
                float ga1 = fmaf(h1[j], whu[1][1], fmaf(h0[j], whu[1][0], f1));
                float gb1 = fmaf(h3[j], whu[1][3], h2[j] * whu[1][2]);
                float ga2 = fmaf(h1[j], whu[2][1], fmaf(h0[j], whu[2][0], bh2u));
                float gb2 = fmaf(h3[j], whu[2][3], h2[j] * whu[2][2]);

                float tr = tanh_ap(ga0 + gb0);        // r = 0.5 + 0.5*tr
                float tz = tanh_ap(ga1 + gb1);        // z = 0.5 + 0.5*tz
                float G2 = ga2 + gb2;                 // 0.5 * g_n
                float n_ = tanh_ap(fmaf(tr, G2, f2 + G2));

                float d  = hp[j] - n_;
                float hn = fmaf(0.5f * d, tz, fmaf(0.5f, d, n_)); // (1-z)n+z*h
                hp[j] = hn;

                h0[j] = __shfl_sync(0xffffffffu, hn, 0, 4);
                h1[j] = __shfl_sync(0xffffffffu, hn, 1, 4);
                h2[j] = __shfl_sync(0xffffffffu, hn, 2, 4);
                h3[j] = __shfl_sync(0xffffffffu, hn, 3, 4);

                // decoder (off-chain); lanes u<2 store slot o=u
                float p = fmaf(h3[j], dwv3, fmaf(h2[j], dwv2,
                          fmaf(h1[j], dwv1, fmaf(h0[j], dwv0, dbv))));
                if (u < 2) ob[j][tt * 2 + u] = p;
            }
        }
        __syncthreads();   // so complete; also guards sx before restaging

        // ---- write output tile: smem -> coalesced float4 STG ----
#pragma unroll
        for (int m = 0; m < 8; m++) {
            int idx = tid + m * THREADS;          // 0..1023
            int r   = idx >> 3;                   // element
            int s4  = idx & 7;                    // float4 index
            float4 v = *(float4*)&so[r * SOS + s4 * 4];
            *(float4*)(outb + (size_t)r * TT * 2 + tc * 2 + s4 * 4) = v;
        }
        __syncthreads();   // so reused next tile
    }
}

extern "C" void kernel_launch(void* const* d_in, const int* in_sizes, int n_in,
                              void* d_out, int out_size) {
    const float* in    = (const float*)d_in[0];
    const float* W_in  = (const float*)d_in[1];
    const float* W_h   = (const float*)d_in[2];
    const float* bias  = (const float*)d_in[3];
    const float* dec_W = (const float*)d_in[4];
    const float* dec_b = (const float*)d_in[5];
    float* out = (float*)d_out;

    tiny_gru6_kernel<<<BB / EPB, THREADS>>>(in, W_in, W_h, bias, dec_W, dec_b, out);
}

// round 9
// speedup vs baseline: 2.9727x; 2.9727x over previous
#include <cuda_runtime.h>
#include <cuda_bf16.h>
#include <cstdint>

// TinyRNN (GRU): B=4096, T=2048, I=3, H=4, O=2
// 4 lanes per element + k=2 elements per thread, 128 blocks x 64 threads
// (256 warps on ~128 SMs): combines R5's SM coverage with R8's ILP interleave.
// h exchange: 3x shfl.bfly (own unit kept in-register, weights xor-permuted).
// Input contributions (f) software-pipelined one step ahead, off the chain.

#define BB 4096
#define TT 2048
#define CHUNK 16
#define EPB 32               // elements per block
#define KK 2                 // elements per thread
#define THREADS 64
#define SXS 52               // sx row stride (CHUNK*3 + 4), float4-aligned
#define SOS 36               // so row stride (CHUNK*2 + 4), float4-aligned

__device__ __forceinline__ float tanh_ap(float x) {
    float r;
    asm("tanh.approx.f32 %0, %1;" : "=f"(r) : "f"(x));
    return r;
}

__global__ __launch_bounds__(THREADS, 1)
void tiny_gru9_kernel(const float* __restrict__ in,     // (B,T,I)
                      const float* __restrict__ W_in,   // (I,3H)
                      const float* __restrict__ W_h,    // (H,3H)
                      const float* __restrict__ bias,   // (6H,)
                      const float* __restrict__ dec_W,  // (H,O)
                      const float* __restrict__ dec_b,  // (O,)
                      float* __restrict__ out)          // (B,T,O)
{
    __shared__ float sx[EPB * SXS];   // staged inputs  [elem][CHUNK*3]
    __shared__ float so[EPB * SOS];   // staged outputs [elem][CHUNK*2]

    const int tid   = threadIdx.x;
    const int u     = tid & 3;        // hidden unit
    const int gbase = tid >> 2;       // lane-group id (0..15)
    const int b0    = blockIdx.x * EPB;

    // ---- weight folding ----
    // r,z: sigmoid(x)=0.5+0.5*tanh(x/2) -> weights & (b_in+b_h) scaled by 0.5
    // n:   tanh direct; recurrent side scaled 0.5 so r*g_n = G2 + tanh(s_r)*G2
    float wiu[3][3];
#pragma unroll
    for (int g = 0; g < 3; g++) {
        float s = (g == 2) ? 1.0f : 0.5f;
#pragma unroll
        for (int i = 0; i < 3; i++) wiu[g][i] = W_in[i * 12 + g * 4 + u] * s;
    }
    // xor-permuted recurrent weights: whx[g][m] multiplies h_{u^m}
    float whx[3][4];
#pragma unroll
    for (int g = 0; g < 3; g++)
#pragma unroll
        for (int m = 0; m < 4; m++)
            whx[g][m] = W_h[(u ^ m) * 12 + g * 4 + u] * 0.5f;

    float bfu0 = 0.5f * (bias[0 + u] + bias[12 + u]);
    float bfu1 = 0.5f * (bias[4 + u] + bias[16 + u]);
    float bfu2 = bias[8 + u];
    float bh2u = 0.5f * bias[20 + u];

    const int o = u & 1;              // decoder slot; lanes u<2 store
    float dwx[4], dbv;                // xor-permuted decoder weights
#pragma unroll
    for (int m = 0; m < 4; m++) dwx[m] = dec_W[(u ^ m) * 2 + o];
    dbv = dec_b[o];

    // recurrent state: own h + 3 neighbors, per element
    float hp[KK], hx1[KK], hx2[KK], hx3[KK];
#pragma unroll
    for (int j = 0; j < KK; j++) { hp[j] = hx1[j] = hx2[j] = hx3[j] = 0.0f; }

    const float* inb  = in  + (size_t)b0 * TT * 3;
    float*       outb = out + (size_t)b0 * TT * 2;

    const float* xb[KK];
    float*       ob[KK];
#pragma unroll
    for (int j = 0; j < KK; j++) {
        xb[j] = &sx[(gbase + 16 * j) * SXS];
        ob[j] = &so[(gbase + 16 * j) * SOS];
    }

    for (int tc = 0; tc < TT; tc += CHUNK) {
        // ---- stage input tile: coalesced float4 LDG -> smem ----
#pragma unroll
        for (int m = 0; m < 6; m++) {
            int idx = tid + m * THREADS;          // 0..383
            int r   = idx / 12;                   // element 0..31
            int s4  = idx - r * 12;               // float4 index 0..11
            float4 v = *(const float4*)(inb + (size_t)r * TT * 3 + tc * 3 + s4 * 4);
            *(float4*)&sx[r * SXS + s4 * 4] = v;
        }
        __syncthreads();

        // ---- prologue: f for step 0 ----
        float fc[KK][3];
#pragma unroll
        for (int j = 0; j < KK; j++) {
            float x0 = xb[j][0], x1 = xb[j][1], x2 = xb[j][2];
            fc[j][0] = fmaf(x2, wiu[0][2], fmaf(x1, wiu[0][1], fmaf(x0, wiu[0][0], bfu0)));
            fc[j][1] = fmaf(x2, wiu[1][2], fmaf(x1, wiu[1][1], fmaf(x0, wiu[1][0], bfu1)));
            fc[j][2] = fmaf(x2, wiu[2][2], fmaf(x1, wiu[2][1], fmaf(x0, wiu[2][0], bfu2)));
        }

        // ---- recurrence: k=2 interleave, f pipelined one step ahead ----
#pragma unroll
        for (int tt = 0; tt < CHUNK; tt++) {
            float fn[KK][3];
            const int tn = (tt + 1 < CHUNK) ? tt + 1 : tt;  // clamped prefetch
#pragma unroll
            for (int j = 0; j < KK; j++) {
                // next step's f: pure issue-slot filler, off the chain
                float y0 = xb[j][tn * 3 + 0];
                float y1 = xb[j][tn * 3 + 1];
                float y2 = xb[j][tn * 3 + 2];
                fn[j][0] = fmaf(y2, wiu[0][2], fmaf(y1, wiu[0][1], fmaf(y0, wiu[0][0], bfu0)));
                fn[j][1] = fmaf(y2, wiu[1][2], fmaf(y1, wiu[1][1], fmaf(y0, wiu[1][0], bfu1)));
                fn[j][2] = fmaf(y2, wiu[2][2], fmaf(y1, wiu[2][1], fmaf(y0, wiu[2][0], bfu2)));

                // gates (chain): roots fc[j][g]; own h first, neighbors after shfl
                float ga0 = fmaf(hx1[j], whx[0][1], fmaf(hp[j], whx[0][0], fc[j][0]));
                float gb0 = fmaf(hx3[j], whx[0][3], hx2[j] * whx[0][2]);
                float ga1 = fmaf(hx1[j], whx[1][1], fmaf(hp[j], whx[1][0], fc[j][1]));
                float gb1 = fmaf(hx3[j], whx[1][3], hx2[j] * whx[1][2]);
                float ga2 = fmaf(hx1[j], whx[2][1], fmaf(hp[j], whx[2][0], bh2u));
                float gb2 = fmaf(hx3[j], whx[2][3], hx2[j] * whx[2][2]);

                float tr = tanh_ap(ga0 + gb0);        // r = 0.5 + 0.5*tr
                float tz = tanh_ap(ga1 + gb1);        // z = 0.5 + 0.5*tz
                float G2 = ga2 + gb2;                 // 0.5 * g_n
                float n_ = tanh_ap(fmaf(tr, G2, fc[j][2] + G2));

                float Z  = fmaf(0.5f, tz, 0.5f);      // off-chain (tz early)
                float d  = hp[j] - n_;
                float hn = fmaf(Z, d, n_);            // (1-z)n + z*h
                hp[j] = hn;

                hx1[j] = __shfl_xor_sync(0xffffffffu, hn, 1, 4);
                hx2[j] = __shfl_xor_sync(0xffffffffu, hn, 2, 4);
                hx3[j] = __shfl_xor_sync(0xffffffffu, hn, 3, 4);

                // decoder (off-chain); lanes u<2 store slot o=u
                float p = fmaf(hx3[j], dwx[3], fmaf(hx2[j], dwx[2],
                          fmaf(hx1[j], dwx[1], fmaf(hn, dwx[0], dbv))));
                if (u < 2) ob[j][tt * 2 + u] = p;

                fc[j][0] = fn[j][0]; fc[j][1] = fn[j][1]; fc[j][2] = fn[j][2];
            }
        }
        __syncthreads();

        // ---- write output tile: smem -> coalesced float4 STG ----
#pragma unroll
        for (int m = 0; m < 4; m++) {
            int idx = tid + m * THREADS;          // 0..255
            int r   = idx >> 3;                   // element 0..31
            int s4  = idx & 7;                    // float4 index
            float4 v = *(float4*)&so[r * SOS + s4 * 4];
            *(float4*)(outb + (size_t)r * TT * 2 + tc * 2 + s4 * 4) = v;
        }
        __syncthreads();   // sx/so reused next tile
    }
}

extern "C" void kernel_launch(void* const* d_in, const int* in_sizes, int n_in,
                              void* d_out, int out_size) {
    const float* in    = (const float*)d_in[0];
    const float* W_in  = (const float*)d_in[1];
    const float* W_h   = (const float*)d_in[2];
    const float* bias  = (const float*)d_in[3];
    const float* dec_W = (const float*)d_in[4];
    const float* dec_b = (const float*)d_in[5];
    float* out = (float*)d_out;

    tiny_gru9_kernel<<<BB / EPB, THREADS>>>(in, W_in, W_h, bias, dec_W, dec_b, out);
}